// round 8
// baseline (speedup 1.0000x reference)
#include <cuda_runtime.h>
#include <cstdint>

// Problem constants: input (64, 65536, 6) f32, output (64, 640) f32.
#define BATCHES     64
#define POINTS      65536
#define PAIRS       (POINTS / 2)            // 32768 pairs per batch
#define F4_PER_B    (POINTS * 6 / 4)        // 98304 float4 per batch
#define NUM_BINS    4
#define NUM_CELLS   64
#define STATS       10
#define FEAT        (NUM_CELLS * STATS)     // 640

// Fused kernel config: 2 blocks per batch, 128 blocks total (single wave,
// one block per SM at 80 KB smem -> all blocks resident, spin-wait is safe).
#define BPB         2
#define T           1024
#define F4_PER_BLK  (F4_PER_B / BPB)        // 49152 (multiple of 3)
#define F4_ITER     (F4_PER_BLK / T)        // 48
#define PAIRS_PER_BLK (PAIRS / BPB)         // 16384
#define ITER        (PAIRS_PER_BLK / T)     // 16
#define REPL        32                      // one smem histogram replica per lane
#define HIST_WORDS  (FEAT * REPL)           // 20480 floats = 80 KB
#define HIST_BYTES  (HIST_WORDS * 4)

// Device scratch (zero at module load; finalizing block restores zeros so
// every graph replay starts from identical state).
__device__ unsigned int g_bbox[BATCHES];
__device__ float        g_sums[BATCHES * FEAT];
__device__ unsigned int g_done[BATCHES];   // bbox-phase arrival counter
__device__ unsigned int g_fin[BATCHES];    // accumulate-phase arrival counter

extern __shared__ float hist[];            // HIST_WORDS floats (80 KB dynamic)

// ---------------------------------------------------------------------------
// Accumulate one point into the per-lane replica histogram.
// Layout: word = (cell*10 + s)*32 + lane  ->  bank == lane, always conflict-free.
// ---------------------------------------------------------------------------
__device__ __forceinline__ void accum_point(
    float* __restrict__ h,   // hist + lane
    float px, float py, float pz,
    float ox, float oy, float oz,
    float bbox, float inv)
{
    float picx = (px + bbox) * inv;
    float picy = (py + bbox) * inv;
    float picz = (pz + bbox) * inv;
    int ix = (int)(picx * 4.0f); ix = min(max(ix, 0), 3);
    int iy = (int)(picy * 4.0f); iy = min(max(iy, 0), 3);
    int iz = (int)(picz * 4.0f); iz = min(max(iz, 0), 3);
    int cell = (ix * NUM_BINS + iy) * NUM_BINS + iz;
    float* d = h + cell * (STATS * REPL);
    atomicAdd(d + 0 * REPL, 1.0f);
    atomicAdd(d + 1 * REPL, picx);
    atomicAdd(d + 2 * REPL, picy);
    atomicAdd(d + 3 * REPL, picz);
    atomicAdd(d + 4 * REPL, ox * ox);
    atomicAdd(d + 5 * REPL, ox * oy);
    atomicAdd(d + 6 * REPL, ox * oz);
    atomicAdd(d + 7 * REPL, oy * oy);
    atomicAdd(d + 8 * REPL, oy * oz);
    atomicAdd(d + 9 * REPL, oz * oz);
}

// ---------------------------------------------------------------------------
// Fused persistent kernel: bbox scan -> per-batch sync -> bin/accumulate ->
// per-batch finalize + L2 normalize + state reset.
// ---------------------------------------------------------------------------
__global__ __launch_bounds__(T) void k_fused(const float4* __restrict__ in4,
                                             float* __restrict__ out) {
    const int batch = blockIdx.y;
    const int half = blockIdx.x;           // 0..BPB-1
    const int tid = threadIdx.x;
    const int lane = tid & 31;

    const float4* pB = in4 + (size_t)batch * F4_PER_B;

    // ================= Phase 1: bbox max over |pos| ========================
    // Unit-stride float4 stream. Point-pair layout (12 floats = 3 float4):
    //   r==0: [p0x p0y p0z o0x]  r==1: [o0y o0z p1x p1y]  r==2: [p1z o1x o1y o1z]
    // -> use x,y,z when r==0; z,w when r==1; x when r==2.
    // Index i = base + tid + k*T with base % 3 == 0 and T % 3 == 1, so the
    // residue advances by exactly 1 each iteration: track it incrementally.
    {
        const int base = half * F4_PER_BLK;
        float m = 0.0f;
        int r = tid % 3;
#pragma unroll 4
        for (int k = 0; k < F4_ITER; k++) {
            float4 v = pB[base + tid + k * T];
            float ax = fabsf(v.x), ay = fabsf(v.y), az = fabsf(v.z), aw = fabsf(v.w);
            float c = (r == 0) ? fmaxf(fmaxf(ax, ay), az)
                    : (r == 1) ? fmaxf(az, aw)
                               : ax;
            m = fmaxf(m, c);
            r = (r == 2) ? 0 : (r + 1);
        }
#pragma unroll
        for (int o = 16; o > 0; o >>= 1)
            m = fmaxf(m, __shfl_xor_sync(0xFFFFFFFFu, m, o));

        __shared__ float sm[T / 32];
        if (lane == 0) sm[tid >> 5] = m;
        __syncthreads();
        if (tid == 0) {
            float mm = sm[0];
#pragma unroll
            for (int i = 1; i < T / 32; i++) mm = fmaxf(mm, sm[i]);
            atomicMax(&g_bbox[batch], __float_as_uint(mm));  // positive floats
            __threadfence();
            atomicAdd(&g_done[batch], 1u);
        }
    }

    // Zero histogram while waiting (independent of peer block).
    float4* h4 = (float4*)hist;
#pragma unroll
    for (int i = tid; i < HIST_WORDS / 4; i += T)
        h4[i] = make_float4(0.f, 0.f, 0.f, 0.f);

    // ================= per-batch sync: wait for both halves ================
    if (tid == 0) {
        volatile unsigned int* dn = &g_done[batch];
        while (*dn < BPB) { }
    }
    __syncthreads();
    __threadfence();   // acquire: peer's atomicMax visible

    const float bbox = __uint_as_float(*(volatile unsigned int*)&g_bbox[batch]);
    const float th = fmaxf(2.0f * bbox, 1e-5f);
    const float inv = 1.0f / th;

    // ================= Phase 2: bin + accumulate ===========================
    {
        const int base = half * PAIRS_PER_BLK;
        float* hrep = hist + lane;
#pragma unroll 2
        for (int k = 0; k < ITER; k++) {
            int j = base + tid + k * T;
            float4 a = pB[3 * j + 0];
            float4 b = pB[3 * j + 1];
            float4 c = pB[3 * j + 2];
            accum_point(hrep, a.x, a.y, a.z, a.w, b.x, b.y, bbox, inv);
            accum_point(hrep, b.z, b.w, c.x, c.y, c.z, c.w, bbox, inv);
        }
    }
    __syncthreads();

    // Reduce 32 replicas per feature; rotate replica order by lane so the
    // 32 lanes of a warp hit 32 distinct banks each step.
    float* sums = g_sums + batch * FEAT;
    if (tid < FEAT) {
        float s = 0.0f;
#pragma unroll
        for (int r = 0; r < REPL; r++)
            s += hist[tid * REPL + ((r + lane) & 31)];
        atomicAdd(&sums[tid], s);
    }

    // ================= Phase 3: last block finalizes =======================
    __shared__ unsigned int s_old;
    __syncthreads();
    if (tid == 0) {
        __threadfence();
        s_old = atomicAdd(&g_fin[batch], 1u);
    }
    __syncthreads();
    if (s_old != BPB - 1) return;
    __threadfence();   // acquire: peer's g_sums additions visible

    __shared__ float wsum[FEAT / 32];
    __shared__ float s_inv;
    float f = 0.0f;
    if (tid < FEAT) {
        const int cell = tid / STATS;
        const int s = tid - cell * STATS;
        float cnt = sums[cell * STATS];
        float val = sums[tid];
        float fc = fmaxf(cnt, 1.0f);
        float up = rsqrtf(fc);
        if (s == 0) {
            f = 0.001f * cnt * up;
        } else if (s < 4) {
            int d = s - 1;
            int ci = (d == 0) ? (cell >> 4) : (d == 1) ? ((cell >> 2) & 3) : (cell & 3);
            float g = ((float)ci + 0.5f) * 0.25f;
            f = (val - cnt * g) * up;
        } else {
            f = val / fc;
        }
    }
    float q = f * f;
#pragma unroll
    for (int o = 16; o > 0; o >>= 1)
        q += __shfl_xor_sync(0xFFFFFFFFu, q, o);
    if (lane == 0 && tid < FEAT) wsum[tid >> 5] = q;
    __syncthreads();

    // reset all per-batch scratch for the next graph replay
    if (tid < FEAT) sums[tid] = 0.0f;
    if (tid == 0) {
        g_bbox[batch] = 0u;
        g_done[batch] = 0u;
        g_fin[batch]  = 0u;
        float ss = 0.0f;
#pragma unroll
        for (int i = 0; i < FEAT / 32; i++) ss += wsum[i];
        s_inv = 1.0f / fmaxf(sqrtf(ss), 1e-12f);
    }
    __syncthreads();
    if (tid < FEAT) out[batch * FEAT + tid] = f * s_inv;
}

// ---------------------------------------------------------------------------
extern "C" void kernel_launch(void* const* d_in, const int* in_sizes, int n_in,
                              void* d_out, int out_size) {
    const float4* in4 = (const float4*)d_in[0];
    float* out = (float*)d_out;
    (void)in_sizes; (void)n_in; (void)out_size;

    cudaFuncSetAttribute(k_fused, cudaFuncAttributeMaxDynamicSharedMemorySize,
                         HIST_BYTES);

    k_fused<<<dim3(BPB, BATCHES), T, HIST_BYTES>>>(in4, out);
}

// round 9
// speedup vs baseline: 1.1038x; 1.1038x over previous
#include <cuda_runtime.h>
#include <cstdint>

// Problem constants: input (64, 65536, 6) f32, output (64, 640) f32.
#define BATCHES     64
#define POINTS      65536
#define PAIRS       (POINTS / 2)            // 32768 pairs per batch
#define F4_PER_B    (POINTS * 6 / 4)        // 98304 float4 per batch
#define NUM_BINS    4
#define NUM_CELLS   64
#define STATS       10
#define FEAT        (NUM_CELLS * STATS)     // 640

// Kernel 1 (bbox) config: flat unit-stride float4 streaming.
#define BPB1        32
#define T1          256
#define F4_PER_BLK1 (F4_PER_B / BPB1)       // 3072 (multiple of 3)
#define ITER1       (F4_PER_BLK1 / T1)      // 12  (MLP per thread)

// Kernel 2 (accumulate + fused finalize) config.
#define BPB2        4                       // 4 x 64 = 256 blocks
#define T2          512
#define PAIRS_PER_BLK2 (PAIRS / BPB2)       // 8192
#define ITER2       (PAIRS_PER_BLK2 / T2)   // 16
#define REPL        32                      // one smem replica per lane
#define HIST_WORDS  (FEAT * REPL)           // 20480 floats = 80 KB
#define HIST_BYTES  (HIST_WORDS * 4)

// Device scratch (zero at module load; finalizing block restores zeros so
// every graph replay starts from identical state).
__device__ unsigned int g_bbox[BATCHES];
__device__ float        g_sums[BATCHES * FEAT];
__device__ unsigned int g_fin[BATCHES];    // accumulate-phase arrival counter

// ---------------------------------------------------------------------------
// Kernel 1: per-batch bbox_max = max(|pos|), flat coalesced float4 stream.
// Point-pair layout (12 floats = 3 float4):
//   r==0: [p0x p0y p0z o0x]  r==1: [o0y o0z p1x p1y]  r==2: [p1z o1x o1y o1z]
// -> pos components: x,y,z when r==0; z,w when r==1; x when r==2.
// i = base + tid + k*T1 with base % 3 == 0 and T1 % 3 == 1, so the residue
// advances by exactly 1 each iteration.
// ---------------------------------------------------------------------------
__global__ __launch_bounds__(T1) void k_bbox(const float4* __restrict__ in4) {
    const int batch = blockIdx.y;
    const int tid = threadIdx.x;
    const float4* pB = in4 + (size_t)batch * F4_PER_B;
    const int base = blockIdx.x * F4_PER_BLK1;

    float m = 0.0f;
    int r = tid % 3;
#pragma unroll
    for (int k = 0; k < ITER1; k++) {
        float4 v = pB[base + tid + k * T1];
        float ax = fabsf(v.x), ay = fabsf(v.y), az = fabsf(v.z), aw = fabsf(v.w);
        float c = (r == 0) ? fmaxf(fmaxf(ax, ay), az)
                : (r == 1) ? fmaxf(az, aw)
                           : ax;
        m = fmaxf(m, c);
        r = (r == 2) ? 0 : (r + 1);
    }
#pragma unroll
    for (int o = 16; o > 0; o >>= 1)
        m = fmaxf(m, __shfl_xor_sync(0xFFFFFFFFu, m, o));

    __shared__ float sm[T1 / 32];
    if ((tid & 31) == 0) sm[tid >> 5] = m;
    __syncthreads();
    if (tid == 0) {
        float mm = sm[0];
#pragma unroll
        for (int i = 1; i < T1 / 32; i++) mm = fmaxf(mm, sm[i]);
        atomicMax(&g_bbox[batch], __float_as_uint(mm));  // positive floats
    }
}

// ---------------------------------------------------------------------------
// Accumulate one point into the per-lane replica histogram.
// Layout: word = (cell*10 + s)*32 + lane  ->  bank == lane, conflict-free.
// ---------------------------------------------------------------------------
__device__ __forceinline__ void accum_point(
    float* __restrict__ h,   // hist + lane
    float px, float py, float pz,
    float ox, float oy, float oz,
    float bbox, float inv)
{
    float picx = (px + bbox) * inv;
    float picy = (py + bbox) * inv;
    float picz = (pz + bbox) * inv;
    int ix = (int)(picx * 4.0f); ix = min(max(ix, 0), 3);
    int iy = (int)(picy * 4.0f); iy = min(max(iy, 0), 3);
    int iz = (int)(picz * 4.0f); iz = min(max(iz, 0), 3);
    int cell = (ix * NUM_BINS + iy) * NUM_BINS + iz;
    float* d = h + cell * (STATS * REPL);
    atomicAdd(d + 0 * REPL, 1.0f);
    atomicAdd(d + 1 * REPL, picx);
    atomicAdd(d + 2 * REPL, picy);
    atomicAdd(d + 3 * REPL, picz);
    atomicAdd(d + 4 * REPL, ox * ox);
    atomicAdd(d + 5 * REPL, ox * oy);
    atomicAdd(d + 6 * REPL, ox * oz);
    atomicAdd(d + 7 * REPL, oy * oy);
    atomicAdd(d + 8 * REPL, oy * oz);
    atomicAdd(d + 9 * REPL, oz * oz);
}

extern __shared__ float hist[];   // HIST_WORDS floats (80 KB dynamic)

// ---------------------------------------------------------------------------
// Kernel 2: bin + accumulate; last block per batch finalizes + L2-normalizes
// + resets scratch (graph-replay safe).
// ---------------------------------------------------------------------------
__global__ __launch_bounds__(T2) void k_accum(const float4* __restrict__ in4,
                                              float* __restrict__ out) {
    const int batch = blockIdx.y;
    const int tid = threadIdx.x;
    const int lane = tid & 31;

    // zero histogram (16B stores)
    float4* h4 = (float4*)hist;
#pragma unroll
    for (int i = tid; i < HIST_WORDS / 4; i += T2)
        h4[i] = make_float4(0.f, 0.f, 0.f, 0.f);
    __syncthreads();

    const float bbox = __uint_as_float(g_bbox[batch]);
    const float th = fmaxf(2.0f * bbox, 1e-5f);
    const float inv = 1.0f / th;

    const float4* p = in4 + (size_t)batch * F4_PER_B;
    const int base = blockIdx.x * PAIRS_PER_BLK2;
    float* hrep = hist + lane;

#pragma unroll 2
    for (int k = 0; k < ITER2; k++) {
        int j = base + tid + k * T2;
        float4 a = p[3 * j + 0];
        float4 b = p[3 * j + 1];
        float4 c = p[3 * j + 2];
        accum_point(hrep, a.x, a.y, a.z, a.w, b.x, b.y, bbox, inv);
        accum_point(hrep, b.z, b.w, c.x, c.y, c.z, c.w, bbox, inv);
    }
    __syncthreads();

    // Reduce 32 replicas per feature; rotate replica order by lane so the
    // 32 lanes of a warp hit 32 distinct banks each step.
    float* sums = g_sums + batch * FEAT;
    for (int w = tid; w < FEAT; w += T2) {
        float s = 0.0f;
#pragma unroll
        for (int r = 0; r < REPL; r++)
            s += hist[w * REPL + ((r + lane) & 31)];
        atomicAdd(&sums[w], s);
    }

    // ---- last block of this batch finalizes ----
    __shared__ unsigned int s_old;
    __syncthreads();
    if (tid == 0) {
        __threadfence();
        s_old = atomicAdd(&g_fin[batch], 1u);
    }
    __syncthreads();
    if (s_old != BPB2 - 1) return;
    __threadfence();   // acquire: peers' g_sums additions visible

    // T2=512 < FEAT=640: each thread handles features tid and tid+512.
    __shared__ float wsum[T2 / 32];
    __shared__ float s_inv;
    float fv0 = 0.0f, fv1 = 0.0f;
    float q = 0.0f;
#pragma unroll
    for (int part = 0; part < 2; part++) {
        int idx = tid + part * T2;
        if (idx < FEAT) {
            const int cell = idx / STATS;
            const int s = idx - cell * STATS;
            float cnt = sums[cell * STATS];
            float val = sums[idx];
            float fc = fmaxf(cnt, 1.0f);
            float up = rsqrtf(fc);
            float f;
            if (s == 0) {
                f = 0.001f * cnt * up;
            } else if (s < 4) {
                int d = s - 1;
                int ci = (d == 0) ? (cell >> 4) : (d == 1) ? ((cell >> 2) & 3) : (cell & 3);
                float g = ((float)ci + 0.5f) * 0.25f;
                f = (val - cnt * g) * up;
            } else {
                f = val / fc;
            }
            if (part == 0) fv0 = f; else fv1 = f;
            q += f * f;
        }
    }
#pragma unroll
    for (int o = 16; o > 0; o >>= 1)
        q += __shfl_xor_sync(0xFFFFFFFFu, q, o);
    if (lane == 0) wsum[tid >> 5] = q;
    __syncthreads();

    // reset scratch for the next replay (all reads of sums are done)
    sums[tid] = 0.0f;
    if (tid < FEAT - T2) sums[tid + T2] = 0.0f;
    if (tid == 0) {
        g_bbox[batch] = 0u;
        g_fin[batch] = 0u;
        float ss = 0.0f;
#pragma unroll
        for (int i = 0; i < T2 / 32; i++) ss += wsum[i];
        s_inv = 1.0f / fmaxf(sqrtf(ss), 1e-12f);
    }
    __syncthreads();

    out[batch * FEAT + tid] = fv0 * s_inv;
    if (tid < FEAT - T2) out[batch * FEAT + tid + T2] = fv1 * s_inv;
}

// ---------------------------------------------------------------------------
extern "C" void kernel_launch(void* const* d_in, const int* in_sizes, int n_in,
                              void* d_out, int out_size) {
    const float4* in4 = (const float4*)d_in[0];
    float* out = (float*)d_out;
    (void)in_sizes; (void)n_in; (void)out_size;

    cudaFuncSetAttribute(k_accum, cudaFuncAttributeMaxDynamicSharedMemorySize,
                         HIST_BYTES);

    k_bbox<<<dim3(BPB1, BATCHES), T1>>>(in4);
    k_accum<<<dim3(BPB2, BATCHES), T2, HIST_BYTES>>>(in4, out);
}

// round 10
// speedup vs baseline: 1.1149x; 1.0101x over previous
#include <cuda_runtime.h>
#include <cstdint>

// Problem constants: input (64, 65536, 6) f32, output (64, 640) f32.
#define BATCHES     64
#define POINTS      65536
#define PAIRS       (POINTS / 2)            // 32768 pairs per batch
#define F4_PER_B    (POINTS * 6 / 4)        // 98304 float4 per batch
#define NUM_BINS    4
#define NUM_CELLS   64
#define STATS       10
#define FEAT        (NUM_CELLS * STATS)     // 640

// Kernel 1 (bbox) config: flat unit-stride float4 streaming.
#define BPB1        32
#define T1          256
#define F4_PER_BLK1 (F4_PER_B / BPB1)       // 3072 (multiple of 3)
#define ITER1       (F4_PER_BLK1 / T1)      // 12  (independent loads in flight)

// Kernel 2 (accumulate) config — exact R3 configuration (49.9us baseline).
#define BPB2        4                       // 4 x 64 = 256 blocks
#define T2          512
#define PAIRS_PER_BLK2 (PAIRS / BPB2)       // 8192
#define ITER2       (PAIRS_PER_BLK2 / T2)   // 16
#define REPL        32                      // one smem replica per lane
#define HIST_WORDS  (FEAT * REPL)           // 20480 floats = 80 KB
#define HIST_BYTES  (HIST_WORDS * 4)

// Device scratch (zero at module load; k_final restores zeros after each use
// so every graph replay sees identical initial state).
__device__ unsigned int g_bbox[BATCHES];
__device__ float        g_sums[BATCHES * FEAT];

// ---------------------------------------------------------------------------
// Kernel 1: per-batch bbox_max = max(|pos|), flat coalesced float4 stream.
// Point-pair layout (12 floats = 3 float4):
//   r==0: [p0x p0y p0z o0x]  r==1: [o0y o0z p1x p1y]  r==2: [p1z o1x o1y o1z]
// -> pos components: x,y,z when r==0; z,w when r==1; x when r==2.
// i = base + tid + k*T1 with base % 3 == 0 and T1 % 3 == 1, so the residue
// advances by exactly 1 each iteration (validated in R8/R9).
// ---------------------------------------------------------------------------
__global__ __launch_bounds__(T1) void k_bbox(const float4* __restrict__ in4) {
    const int batch = blockIdx.y;
    const int tid = threadIdx.x;
    const float4* pB = in4 + (size_t)batch * F4_PER_B;
    const int base = blockIdx.x * F4_PER_BLK1;

    float m = 0.0f;
    int r = tid % 3;
#pragma unroll
    for (int k = 0; k < ITER1; k++) {
        float4 v = pB[base + tid + k * T1];
        float ax = fabsf(v.x), ay = fabsf(v.y), az = fabsf(v.z), aw = fabsf(v.w);
        float c = (r == 0) ? fmaxf(fmaxf(ax, ay), az)
                : (r == 1) ? fmaxf(az, aw)
                           : ax;
        m = fmaxf(m, c);
        r = (r == 2) ? 0 : (r + 1);
    }
#pragma unroll
    for (int o = 16; o > 0; o >>= 1)
        m = fmaxf(m, __shfl_xor_sync(0xFFFFFFFFu, m, o));

    __shared__ float sm[T1 / 32];
    if ((tid & 31) == 0) sm[tid >> 5] = m;
    __syncthreads();
    if (tid == 0) {
        float mm = sm[0];
#pragma unroll
        for (int i = 1; i < T1 / 32; i++) mm = fmaxf(mm, sm[i]);
        atomicMax(&g_bbox[batch], __float_as_uint(mm));  // positive floats
    }
}

// ---------------------------------------------------------------------------
// Kernel 2: bin points, accumulate (count, sum_pic, sum_cov) per cell.
// Per-lane replica with bank-exact layout:
//   word addr = (cell*10 + s)*32 + lane   ->  bank == lane, always.
// Shared-memory atomics conflict-free by construction.  (R3-identical.)
// ---------------------------------------------------------------------------
__device__ __forceinline__ void accum_point(
    float* __restrict__ h,   // hist + lane
    float px, float py, float pz,
    float ox, float oy, float oz,
    float bbox, float inv)
{
    float picx = (px + bbox) * inv;
    float picy = (py + bbox) * inv;
    float picz = (pz + bbox) * inv;
    int ix = (int)(picx * 4.0f); ix = min(max(ix, 0), 3);
    int iy = (int)(picy * 4.0f); iy = min(max(iy, 0), 3);
    int iz = (int)(picz * 4.0f); iz = min(max(iz, 0), 3);
    int cell = (ix * NUM_BINS + iy) * NUM_BINS + iz;
    float* d = h + cell * (STATS * REPL);
    atomicAdd(d + 0 * REPL, 1.0f);
    atomicAdd(d + 1 * REPL, picx);
    atomicAdd(d + 2 * REPL, picy);
    atomicAdd(d + 3 * REPL, picz);
    atomicAdd(d + 4 * REPL, ox * ox);
    atomicAdd(d + 5 * REPL, ox * oy);
    atomicAdd(d + 6 * REPL, ox * oz);
    atomicAdd(d + 7 * REPL, oy * oy);
    atomicAdd(d + 8 * REPL, oy * oz);
    atomicAdd(d + 9 * REPL, oz * oz);
}

extern __shared__ float hist[];   // HIST_WORDS floats (80 KB dynamic)

__global__ __launch_bounds__(T2) void k_accum(const float4* __restrict__ in4) {
    const int batch = blockIdx.y;
    const int tid = threadIdx.x;
    const int lane = tid & 31;

    // zero histogram (16B vector stores)
    float4* h4 = (float4*)hist;
#pragma unroll
    for (int i = tid; i < HIST_WORDS / 4; i += T2)
        h4[i] = make_float4(0.f, 0.f, 0.f, 0.f);
    __syncthreads();

    const float bbox = __uint_as_float(g_bbox[batch]);
    const float th = fmaxf(2.0f * bbox, 1e-5f);
    const float inv = 1.0f / th;

    const float4* p = in4 + (size_t)batch * F4_PER_B;
    const int base = blockIdx.x * PAIRS_PER_BLK2;
    float* hrep = hist + lane;

#pragma unroll 2
    for (int k = 0; k < ITER2; k++) {
        int j = base + tid + k * T2;
        float4 a = p[3 * j + 0];
        float4 b = p[3 * j + 1];
        float4 c = p[3 * j + 2];
        accum_point(hrep, a.x, a.y, a.z, a.w, b.x, b.y, bbox, inv);
        accum_point(hrep, b.z, b.w, c.x, c.y, c.z, c.w, bbox, inv);
    }
    __syncthreads();

    // Reduce 32 replicas per feature; rotate replica order by lane so the
    // 32 lanes of a warp hit 32 distinct banks each step.
    for (int w = tid; w < FEAT; w += T2) {
        float s = 0.0f;
#pragma unroll
        for (int r = 0; r < REPL; r++)
            s += hist[w * REPL + ((r + lane) & 31)];
        atomicAdd(&g_sums[batch * FEAT + w], s);
    }
}

// ---------------------------------------------------------------------------
// Kernel 3: finalize. One block per batch, 640 threads = one (cell, stat).
//   f_freq    = 0.001 * n * rsqrt(max(n,1))
//   f_mean[d] = (sum_pic[d] - n * grid[d]) * rsqrt(max(n,1))
//   f_cov     = sum_cov / max(n,1)
// then L2-normalize the 640-vector; restore scratch to zero for next replay.
// ---------------------------------------------------------------------------
__global__ __launch_bounds__(FEAT) void k_final(float* __restrict__ out) {
    const int b = blockIdx.x;
    const int t = threadIdx.x;               // 0..639
    const int cell = t / STATS;
    const int s = t - cell * STATS;

    float* sums = g_sums + b * FEAT;
    float cnt = sums[cell * STATS];
    float val = sums[t];
    float fc = fmaxf(cnt, 1.0f);
    float up = rsqrtf(fc);

    float f;
    if (s == 0) {
        f = 0.001f * cnt * up;
    } else if (s < 4) {
        int d = s - 1;
        int ci = (d == 0) ? (cell >> 4) : (d == 1) ? ((cell >> 2) & 3) : (cell & 3);
        float g = ((float)ci + 0.5f) * 0.25f;
        f = (val - cnt * g) * up;
    } else {
        f = val / fc;
    }

    float q = f * f;
#pragma unroll
    for (int o = 16; o > 0; o >>= 1)
        q += __shfl_xor_sync(0xFFFFFFFFu, q, o);

    __shared__ float wsum[FEAT / 32];
    __shared__ float s_inv;
    if ((t & 31) == 0) wsum[t >> 5] = q;
    __syncthreads();

    // all reads of g_sums done -> restore zeros for the next replay
    sums[t] = 0.0f;
    if (t == 0) {
        g_bbox[b] = 0u;
        float ss = 0.0f;
#pragma unroll
        for (int i = 0; i < FEAT / 32; i++) ss += wsum[i];
        s_inv = 1.0f / fmaxf(sqrtf(ss), 1e-12f);
    }
    __syncthreads();

    out[b * FEAT + t] = f * s_inv;
}

// ---------------------------------------------------------------------------
extern "C" void kernel_launch(void* const* d_in, const int* in_sizes, int n_in,
                              void* d_out, int out_size) {
    const float4* in4 = (const float4*)d_in[0];
    float* out = (float*)d_out;
    (void)in_sizes; (void)n_in; (void)out_size;

    cudaFuncSetAttribute(k_accum, cudaFuncAttributeMaxDynamicSharedMemorySize,
                         HIST_BYTES);

    k_bbox<<<dim3(BPB1, BATCHES), T1>>>(in4);
    k_accum<<<dim3(BPB2, BATCHES), T2, HIST_BYTES>>>(in4);
    k_final<<<BATCHES, FEAT>>>(out);
}

// round 11
// speedup vs baseline: 1.2488x; 1.1201x over previous
#include <cuda_runtime.h>
#include <cstdint>

// Problem constants: input (64, 65536, 6) f32, output (64, 640) f32.
#define BATCHES     64
#define POINTS      65536
#define PAIRS       (POINTS / 2)            // 32768 pairs per batch
#define F4_PER_B    (POINTS * 6 / 4)        // 98304 float4 per batch
#define NUM_BINS    4
#define NUM_CELLS   64
#define STATS       10
#define FEAT        (NUM_CELLS * STATS)     // 640

// Kernel 1 (bbox) config — exact R3 strided config (18.6us, 70.9% DRAM).
#define BPB1        32
#define T1          256
#define PAIRS_PER_BLK1 (PAIRS / BPB1)       // 1024
#define ITER1       (PAIRS_PER_BLK1 / T1)   // 4

// Kernel 2 (accumulate) config — exact R3 configuration.
#define BPB2        4                       // 4 x 64 = 256 blocks
#define T2          512
#define PAIRS_PER_BLK2 (PAIRS / BPB2)       // 8192
#define ITER2       (PAIRS_PER_BLK2 / T2)   // 16
#define REPL        32                      // one smem replica per lane
#define HIST_WORDS  (FEAT * REPL)           // 20480 floats = 80 KB
#define HIST_BYTES  (HIST_WORDS * 4)

// Device scratch (zero at module load; k_final restores zeros after each use
// so every graph replay sees identical initial state).
__device__ unsigned int g_bbox[BATCHES];
__device__ float        g_sums[BATCHES * FEAT];

// ---------------------------------------------------------------------------
// Kernel 1: per-batch bbox_max = max(|pos|), strided pair loads (R3-exact).
// Layout per point pair (12 floats = 3 float4):
//   a = [p0x p0y p0z o0x]  b = [o0y o0z p1x p1y]  c = [p1z o1x o1y o1z]
// ---------------------------------------------------------------------------
__global__ __launch_bounds__(T1) void k_bbox(const float4* __restrict__ in4) {
    const int batch = blockIdx.y;
    const int tid = threadIdx.x;
    const float4* p = in4 + (size_t)batch * F4_PER_B;
    const int base = blockIdx.x * PAIRS_PER_BLK1;

    float m = 0.0f;
#pragma unroll
    for (int k = 0; k < ITER1; k++) {
        int j = base + tid + k * T1;
        float4 a = p[3 * j + 0];
        float4 b = p[3 * j + 1];
        float4 c = p[3 * j + 2];
        m = fmaxf(m, fmaxf(fmaxf(fabsf(a.x), fabsf(a.y)), fabsf(a.z)));
        m = fmaxf(m, fmaxf(fmaxf(fabsf(b.z), fabsf(b.w)), fabsf(c.x)));
    }
#pragma unroll
    for (int o = 16; o > 0; o >>= 1)
        m = fmaxf(m, __shfl_xor_sync(0xFFFFFFFFu, m, o));

    __shared__ float sm[T1 / 32];
    if ((tid & 31) == 0) sm[tid >> 5] = m;
    __syncthreads();
    if (tid == 0) {
        float mm = sm[0];
#pragma unroll
        for (int i = 1; i < T1 / 32; i++) mm = fmaxf(mm, sm[i]);
        atomicMax(&g_bbox[batch], __float_as_uint(mm));  // positive floats
        // All of this block's work is globally visible after the atomic above;
        // let the dependent k_accum start dispatching.
        cudaTriggerProgrammaticLaunchCompletion();
    }
}

// ---------------------------------------------------------------------------
// Kernel 2: bin points, accumulate (count, sum_pic, sum_cov) per cell.
// Per-lane replica, bank-exact layout: word = (cell*10+s)*32 + lane.
// ---------------------------------------------------------------------------
__device__ __forceinline__ void accum_point(
    float* __restrict__ h,   // hist + lane
    float px, float py, float pz,
    float ox, float oy, float oz,
    float bbox, float inv)
{
    float picx = (px + bbox) * inv;
    float picy = (py + bbox) * inv;
    float picz = (pz + bbox) * inv;
    int ix = (int)(picx * 4.0f); ix = min(max(ix, 0), 3);
    int iy = (int)(picy * 4.0f); iy = min(max(iy, 0), 3);
    int iz = (int)(picz * 4.0f); iz = min(max(iz, 0), 3);
    int cell = (ix * NUM_BINS + iy) * NUM_BINS + iz;
    float* d = h + cell * (STATS * REPL);
    atomicAdd(d + 0 * REPL, 1.0f);
    atomicAdd(d + 1 * REPL, picx);
    atomicAdd(d + 2 * REPL, picy);
    atomicAdd(d + 3 * REPL, picz);
    atomicAdd(d + 4 * REPL, ox * ox);
    atomicAdd(d + 5 * REPL, ox * oy);
    atomicAdd(d + 6 * REPL, ox * oz);
    atomicAdd(d + 7 * REPL, oy * oy);
    atomicAdd(d + 8 * REPL, oy * oz);
    atomicAdd(d + 9 * REPL, oz * oz);
}

extern __shared__ float hist[];   // HIST_WORDS floats (80 KB dynamic)

__global__ __launch_bounds__(T2) void k_accum(const float4* __restrict__ in4) {
    const int batch = blockIdx.y;
    const int tid = threadIdx.x;
    const int lane = tid & 31;

    // PDL preamble: zero the histogram BEFORE waiting on k_bbox — this runs
    // concurrently with the bbox kernel's tail.
    float4* h4 = (float4*)hist;
#pragma unroll
    for (int i = tid; i < HIST_WORDS / 4; i += T2)
        h4[i] = make_float4(0.f, 0.f, 0.f, 0.f);

    cudaGridDependencySynchronize();   // wait: k_bbox complete + visible
    __syncthreads();

    const float bbox = __uint_as_float(g_bbox[batch]);
    const float th = fmaxf(2.0f * bbox, 1e-5f);
    const float inv = 1.0f / th;

    const float4* p = in4 + (size_t)batch * F4_PER_B;
    const int base = blockIdx.x * PAIRS_PER_BLK2;
    float* hrep = hist + lane;

#pragma unroll 2
    for (int k = 0; k < ITER2; k++) {
        int j = base + tid + k * T2;
        float4 a = p[3 * j + 0];
        float4 b = p[3 * j + 1];
        float4 c = p[3 * j + 2];
        accum_point(hrep, a.x, a.y, a.z, a.w, b.x, b.y, bbox, inv);
        accum_point(hrep, b.z, b.w, c.x, c.y, c.z, c.w, bbox, inv);
    }
    __syncthreads();

    // Reduce 32 replicas per feature; rotate replica order by lane so the
    // 32 lanes of a warp hit 32 distinct banks each step.
    for (int w = tid; w < FEAT; w += T2) {
        float s = 0.0f;
#pragma unroll
        for (int r = 0; r < REPL; r++)
            s += hist[w * REPL + ((r + lane) & 31)];
        atomicAdd(&g_sums[batch * FEAT + w], s);
    }
    __syncthreads();
    if (tid == 0) cudaTriggerProgrammaticLaunchCompletion();
}

// ---------------------------------------------------------------------------
// Kernel 3: finalize. One block per batch, 640 threads = one (cell, stat).
// L2-normalize the 640-vector; restore scratch to zero for next replay.
// ---------------------------------------------------------------------------
__global__ __launch_bounds__(FEAT) void k_final(float* __restrict__ out) {
    cudaGridDependencySynchronize();   // wait: k_accum complete + visible

    const int b = blockIdx.x;
    const int t = threadIdx.x;               // 0..639
    const int cell = t / STATS;
    const int s = t - cell * STATS;

    float* sums = g_sums + b * FEAT;
    float cnt = sums[cell * STATS];
    float val = sums[t];
    float fc = fmaxf(cnt, 1.0f);
    float up = rsqrtf(fc);

    float f;
    if (s == 0) {
        f = 0.001f * cnt * up;
    } else if (s < 4) {
        int d = s - 1;
        int ci = (d == 0) ? (cell >> 4) : (d == 1) ? ((cell >> 2) & 3) : (cell & 3);
        float g = ((float)ci + 0.5f) * 0.25f;
        f = (val - cnt * g) * up;
    } else {
        f = val / fc;
    }

    float q = f * f;
#pragma unroll
    for (int o = 16; o > 0; o >>= 1)
        q += __shfl_xor_sync(0xFFFFFFFFu, q, o);

    __shared__ float wsum[FEAT / 32];
    __shared__ float s_inv;
    if ((t & 31) == 0) wsum[t >> 5] = q;
    __syncthreads();

    // all reads of g_sums done -> restore zeros for the next replay
    sums[t] = 0.0f;
    if (t == 0) {
        g_bbox[b] = 0u;
        float ss = 0.0f;
#pragma unroll
        for (int i = 0; i < FEAT / 32; i++) ss += wsum[i];
        s_inv = 1.0f / fmaxf(sqrtf(ss), 1e-12f);
    }
    __syncthreads();

    out[b * FEAT + t] = f * s_inv;
}

// ---------------------------------------------------------------------------
extern "C" void kernel_launch(void* const* d_in, const int* in_sizes, int n_in,
                              void* d_out, int out_size) {
    const float4* in4 = (const float4*)d_in[0];
    float* out = (float*)d_out;
    (void)in_sizes; (void)n_in; (void)out_size;

    cudaFuncSetAttribute(k_accum, cudaFuncAttributeMaxDynamicSharedMemorySize,
                         HIST_BYTES);

    // k_bbox: normal launch (producer).
    k_bbox<<<dim3(BPB1, BATCHES), T1>>>(in4);

    // k_accum: programmatic dependent launch on k_bbox.
    {
        cudaLaunchAttribute a[1];
        a[0].id = cudaLaunchAttributeProgrammaticStreamSerialization;
        a[0].val.programmaticStreamSerializationAllowed = 1;
        cudaLaunchConfig_t cfg{};
        cfg.gridDim = dim3(BPB2, BATCHES);
        cfg.blockDim = dim3(T2);
        cfg.dynamicSmemBytes = HIST_BYTES;
        cfg.stream = 0;
        cfg.attrs = a;
        cfg.numAttrs = 1;
        cudaLaunchKernelEx(&cfg, k_accum, in4);
    }

    // k_final: programmatic dependent launch on k_accum.
    {
        cudaLaunchAttribute a[1];
        a[0].id = cudaLaunchAttributeProgrammaticStreamSerialization;
        a[0].val.programmaticStreamSerializationAllowed = 1;
        cudaLaunchConfig_t cfg{};
        cfg.gridDim = dim3(BATCHES);
        cfg.blockDim = dim3(FEAT);
        cfg.dynamicSmemBytes = 0;
        cfg.stream = 0;
        cfg.attrs = a;
        cfg.numAttrs = 1;
        cudaLaunchKernelEx(&cfg, k_final, out);
    }
}